// round 6
// baseline (speedup 1.0000x reference)
#include <cuda_runtime.h>
#include <cuda_fp16.h>

#define NN 100000
#define NE 1000000
#define DD 64
#define NRELTAB 401
#define BB 8

#define BM 128
#define TM 8
#define GEMM_THREADS 256
#define NGEMM_BLOCKS ((NN + BM - 1) / BM)        // 782
#define NPROJ_ROWS (2 * NRELTAB + BB)            // 810
#define NPROJ_BLOCKS ((NPROJ_ROWS + 3) / 4)      // 203
#define PRE_SMEM ((BM * DD + 2 * DD * DD) * 4 + 1024)

#define EDGE_BLOCKS 592      // 4 waves of 148 SMs
#define EDGE_THREADS 256
#define EDGE_GROUPS (EDGE_BLOCKS * (EDGE_THREADS / 16))   // 9472

// Scratch (static device globals — no runtime allocation).
// g_h16: per node, 128 halves: for l in 0..15: hsp[4l..4l+3] then hp2[4l..4l+3]
//   (hsp = hidden@Ws^T, hp2 = hidden@Wh^T)  -> one LDG.128 per lane in edge kernel
__device__ __align__(256) __half g_h16[NN * 2 * DD];
// g_trrp: per relation, 128 halves: for l: tr[4l..4l+3], rp2[4l..4l+3]
//   (tr = rel_emb@Wr^T, rp2 = rel_emb@Wh^T)
__device__ __align__(256) __half g_trrp[NRELTAB * 2 * DD];
// g_tqr16: rel_emb[q_rel]@Wqr^T + bias, fp16
__device__ __align__(256) __half g_tqr16[BB * DD];

// ---------------------------------------------------------------------------
// Fused front kernel.
//  blocks [0, NGEMM_BLOCKS): zero d_out slice + dual-output SGEMM tile
//     -> g_h16 (interleaved fp16). Near fp32-FFMA roofline already.
//  blocks [NGEMM_BLOCKS, +NPROJ_BLOCKS): relation projections, 4 rows/block:
//     rid in [0,401):   tr  -> g_trrp (even 4-blocks)
//     rid in [401,802): rp2 -> g_trrp (odd 4-blocks)
//     rid in [802,810): tqr -> g_tqr16
// ---------------------------------------------------------------------------
__global__ __launch_bounds__(GEMM_THREADS)
void fused_pre_kernel(const float* __restrict__ hidden,
                      const float* __restrict__ Ws,
                      const float* __restrict__ Wh,
                      const float* __restrict__ emb,
                      const float* __restrict__ Wr,
                      const float* __restrict__ Wqr,
                      const float* __restrict__ bias,
                      const int* __restrict__ qrel,
                      float* __restrict__ out) {
    extern __shared__ float sm[];
    int t = threadIdx.x;

    if (blockIdx.x < NGEMM_BLOCKS) {
        // zero the output buffer (edge kernel REDs into it)
        {
            int i = blockIdx.x * GEMM_THREADS + t;
            int stride = NGEMM_BLOCKS * GEMM_THREADS;
            float4* p = (float4*)out;
            const int n4 = NN * DD / 4;
            for (int j = i; j < n4; j += stride)
                p[j] = make_float4(0.f, 0.f, 0.f, 0.f);
        }

        float* Asm = sm;                 // [128][64]
        float* Wt1 = sm + BM * DD;       // Ws^T as [k][a]
        float* Wt2 = Wt1 + DD * DD;      // Wh^T as [k][a]

        for (int i = t; i < DD * DD / 4; i += GEMM_THREADS) {
            int a = i >> 4, k = (i & 15) * 4;
            float4 w = ((const float4*)Ws)[i];
            Wt1[(k + 0) * DD + a] = w.x; Wt1[(k + 1) * DD + a] = w.y;
            Wt1[(k + 2) * DD + a] = w.z; Wt1[(k + 3) * DD + a] = w.w;
            float4 v = ((const float4*)Wh)[i];
            Wt2[(k + 0) * DD + a] = v.x; Wt2[(k + 1) * DD + a] = v.y;
            Wt2[(k + 2) * DD + a] = v.z; Wt2[(k + 3) * DD + a] = v.w;
        }
        int row0 = blockIdx.x * BM;
        for (int i = t; i < BM * DD / 4; i += GEMM_THREADS) {
            int m = i >> 4;
            float4 v = make_float4(0.f, 0.f, 0.f, 0.f);
            if (row0 + m < NN)
                v = ((const float4*)(hidden + (size_t)(row0 + m) * DD))[i & 15];
            ((float4*)Asm)[i] = v;
        }
        __syncthreads();

        int rt = t >> 4, ct = t & 15;
        const float* arow = Asm + rt * TM * DD;
        const float4* w1p = (const float4*)Wt1 + ct;
        const float4* w2p = (const float4*)Wt2 + ct;

        float4 acc1[TM], acc2[TM];
#pragma unroll
        for (int r = 0; r < TM; r++) {
            acc1[r] = make_float4(0.f, 0.f, 0.f, 0.f);
            acc2[r] = make_float4(0.f, 0.f, 0.f, 0.f);
        }

#pragma unroll 4
        for (int k = 0; k < DD; k++) {
            float4 w1 = w1p[k * 16];
            float4 w2 = w2p[k * 16];
#pragma unroll
            for (int r = 0; r < TM; r++) {
                float a = arow[r * DD + k];
                acc1[r].x = fmaf(a, w1.x, acc1[r].x);
                acc1[r].y = fmaf(a, w1.y, acc1[r].y);
                acc1[r].z = fmaf(a, w1.z, acc1[r].z);
                acc1[r].w = fmaf(a, w1.w, acc1[r].w);
                acc2[r].x = fmaf(a, w2.x, acc2[r].x);
                acc2[r].y = fmaf(a, w2.y, acc2[r].y);
                acc2[r].z = fmaf(a, w2.z, acc2[r].z);
                acc2[r].w = fmaf(a, w2.w, acc2[r].w);
            }
        }

#pragma unroll
        for (int r = 0; r < TM; r++) {
            int m = row0 + rt * TM + r;
            if (m < NN) {
                uint4 h;  // hsp 4 halves | hp2 4 halves (interleaved layout)
                ((__half2*)&h)[0] = __floats2half2_rn(acc1[r].x, acc1[r].y);
                ((__half2*)&h)[1] = __floats2half2_rn(acc1[r].z, acc1[r].w);
                ((__half2*)&h)[2] = __floats2half2_rn(acc2[r].x, acc2[r].y);
                ((__half2*)&h)[3] = __floats2half2_rn(acc2[r].z, acc2[r].w);
                ((uint4*)(g_h16 + (size_t)m * 2 * DD))[ct] = h;
            }
        }
        return;
    }

    // ---- relation projection path: 4 rows/block, 64 threads per row ----
    float* WrS  = sm;               // [64][65]
    float* WhS  = sm + DD * 65;     // [64][65]
    float* WqrS = sm + 2 * DD * 65; // [64][65]
    float* rows = sm + 3 * DD * 65; // [4][64]
    for (int i = t; i < DD * DD; i += GEMM_THREADS) {
        int r = i >> 6, c = i & 63;
        WrS [r * 65 + c] = Wr[i];
        WhS [r * 65 + c] = Wh[i];
        WqrS[r * 65 + c] = Wqr[i];
    }
    int sub = t >> 6, a = t & 63;
    int rid = (blockIdx.x - NGEMM_BLOCKS) * 4 + sub;
    bool valid = rid < NPROJ_ROWS;
    int seg = valid ? ((rid >= 2 * NRELTAB) ? 2 : (rid >= NRELTAB) ? 1 : 0) : 0;
    int r = rid - (seg == 2 ? 2 * NRELTAB : seg == 1 ? NRELTAB : 0);
    int src = valid ? (seg == 2 ? qrel[r] : r) : 0;
    rows[sub * DD + a] = emb[src * DD + a];
    __syncthreads();
    if (!valid) return;

    const float* W = (seg == 2) ? WqrS : (seg == 1) ? WhS : WrS;
    const float* rw = rows + sub * DD;
    float acc = (seg == 2) ? bias[a] : 0.f;
#pragma unroll
    for (int k = 0; k < DD; k++) acc = fmaf(rw[k], W[a * 65 + k], acc);

    __half h = __float2half(acc);
    if (seg == 2) {
        g_tqr16[r * DD + a] = h;
    } else {
        // interleaved: tr at halves 8*(a/4)+(a%4), rp2 at +4
        int pos = r * 2 * DD + 8 * (a >> 2) + (a & 3) + (seg == 1 ? 4 : 0);
        g_trrp[pos] = h;
    }
}

// ---------------------------------------------------------------------------
// Persistent edge kernel: 16 lanes/edge, grid-stride over edges.
// Per warp (2 edges) L1tex wavefronts: idx 1 + h16 4 + trrp 4 + tq 2 + RED 4
// = 15 (was ~25) -> predicted ~57us at the 1 wf/cyc/SM L1tex rate.
//   alpha = sigmoid( dot(relu(hsp[sub] + tr[rel] + tqr[r_idx]), w) + b )
//   red.global.add.v4.f32 of alpha*(hp2[sub] + rp2[rel]) directly into OUT
// ---------------------------------------------------------------------------
__global__ __launch_bounds__(EDGE_THREADS)
void edge_kernel(const int* __restrict__ edges,
                 const float* __restrict__ walpha_w,
                 const float* __restrict__ walpha_b,
                 float* __restrict__ out) {
    const int l = threadIdx.x & 15;
    const int c = l * 4;
    const float4 wv = __ldg((const float4*)walpha_w + l);
    const float wb = __ldg(walpha_b);
    // all shfls use the 16-lane half-warp mask: trip counts can differ by one
    // across half-warps at the grid-stride boundary
    const unsigned hmask = 0xFFFFu << (threadIdx.x & 16);

    unsigned group = blockIdx.x * (EDGE_THREADS / 16) + (threadIdx.x >> 4);

    for (unsigned eid = group; eid < NE; eid += EDGE_GROUPS) {
        const int* e = edges + (size_t)eid * 6;
        int v = 0;
        if (l < 4) v = __ldg(e + ((0x5420u >> (l * 4)) & 0xF));  // cols 0,2,4,5
        int r_idx = __shfl_sync(hmask, v, 0, 16);
        int rel   = __shfl_sync(hmask, v, 1, 16);
        int sub   = __shfl_sync(hmask, v, 2, 16);
        int obj   = __shfl_sync(hmask, v, 3, 16);

        uint4 h  = __ldg((const uint4*)(g_h16 + (size_t)sub * 2 * DD) + l);
        uint4 tt = __ldg((const uint4*)(g_trrp + rel * 2 * DD) + l);
        uint2 tq = __ldg((const uint2*)(g_tqr16 + r_idx * DD) + l);

        float2 a0 = __half22float2(*(const __half2*)&h.x);   // hsp[4l..4l+1]
        float2 a1 = __half22float2(*(const __half2*)&h.y);   // hsp[4l+2..3]
        float2 b0 = __half22float2(*(const __half2*)&h.z);   // hp2[4l..4l+1]
        float2 b1 = __half22float2(*(const __half2*)&h.w);
        float2 t0 = __half22float2(*(const __half2*)&tt.x);  // tr
        float2 t1 = __half22float2(*(const __half2*)&tt.y);
        float2 r0 = __half22float2(*(const __half2*)&tt.z);  // rp2
        float2 r1 = __half22float2(*(const __half2*)&tt.w);
        float2 q0 = __half22float2(*(const __half2*)&tq.x);
        float2 q1 = __half22float2(*(const __half2*)&tq.y);

        float p0 = fmaxf(a0.x + t0.x + q0.x, 0.f);
        float p1 = fmaxf(a0.y + t0.y + q0.y, 0.f);
        float p2 = fmaxf(a1.x + t1.x + q1.x, 0.f);
        float p3 = fmaxf(a1.y + t1.y + q1.y, 0.f);
        float part = fmaf(p0, wv.x, fmaf(p1, wv.y, fmaf(p2, wv.z, p3 * wv.w)));
#pragma unroll
        for (int o = 8; o > 0; o >>= 1)
            part += __shfl_xor_sync(hmask, part, o);

        float alpha = 1.f / (1.f + __expf(-(part + wb)));

        float m0 = alpha * (b0.x + r0.x);
        float m1 = alpha * (b0.y + r0.y);
        float m2 = alpha * (b1.x + r1.x);
        float m3 = alpha * (b1.y + r1.y);

        float* dst = out + (size_t)obj * DD + c;
        asm volatile("red.global.add.v4.f32 [%0], {%1, %2, %3, %4};"
                     :: "l"(dst), "f"(m0), "f"(m1), "f"(m2), "f"(m3)
                     : "memory");
    }
}

// ---------------------------------------------------------------------------
// Inputs (metadata order):
//  0 q_sub[8] i32, 1 q_rel[8] i32, 2 hidden[100000,64] f32, 3 edges[1000000,6] i32,
//  4 nodes[100000,2] i32, 5 old_nodes_new_idx[50000] i32, 6 batchsize i32,
//  7 rel_emb[401,64] f32, 8 Ws[64,64], 9 Wr[64,64], 10 Wqr_w[64,64], 11 Wqr_b[64],
// 12 walpha_w[1,64], 13 walpha_b[1], 14 Wh[64,64]
// Output: hidden_new[100000,64] f32
// ---------------------------------------------------------------------------
extern "C" void kernel_launch(void* const* d_in, const int* in_sizes, int n_in,
                              void* d_out, int out_size) {
    const int*   q_rel    = (const int*)d_in[1];
    const float* hidden   = (const float*)d_in[2];
    const int*   edges    = (const int*)d_in[3];
    const float* rel_emb  = (const float*)d_in[7];
    const float* Ws       = (const float*)d_in[8];
    const float* Wr       = (const float*)d_in[9];
    const float* Wqr_w    = (const float*)d_in[10];
    const float* Wqr_b    = (const float*)d_in[11];
    const float* walpha_w = (const float*)d_in[12];
    const float* walpha_b = (const float*)d_in[13];
    const float* Wh       = (const float*)d_in[14];
    float* out = (float*)d_out;

    cudaFuncSetAttribute(fused_pre_kernel,
                         cudaFuncAttributeMaxDynamicSharedMemorySize, PRE_SMEM);

    fused_pre_kernel<<<NGEMM_BLOCKS + NPROJ_BLOCKS, GEMM_THREADS, PRE_SMEM>>>(
        hidden, Ws, Wh, rel_emb, Wr, Wqr_w, Wqr_b, q_rel, out);
    edge_kernel<<<EDGE_BLOCKS, EDGE_THREADS>>>(edges, walpha_w, walpha_b, out);
}

// round 7
// speedup vs baseline: 1.0945x; 1.0945x over previous
#include <cuda_runtime.h>
#include <cuda_fp16.h>

#define NN 100000
#define NE 1000000
#define DD 64
#define NRELTAB 401
#define BB 8

#define BM 128
#define TM 8
#define GEMM_THREADS 256
#define NGEMM_BLOCKS ((NN + BM - 1) / BM)        // 782
#define NPROJ_ROWS (2 * NRELTAB + BB)            // 810
#define NPROJ_BLOCKS ((NPROJ_ROWS + 3) / 4)      // 203
#define PRE_SMEM ((BM * DD + 2 * DD * DD) * 4 + 1024)

// Scratch (static device globals — no runtime allocation).
// g_h16: per node, 128 halves: for l in 0..15: hsp[4l..4l+3] then hp2[4l..4l+3]
//   (hsp = hidden@Ws^T, hp2 = hidden@Wh^T)  -> one LDG.128 per lane in edge kernel
__device__ __align__(256) __half g_h16[NN * 2 * DD];
// g_trrp: per relation, 128 halves: for l: tr[4l..4l+3], rp2[4l..4l+3]
//   (tr = rel_emb@Wr^T, rp2 = rel_emb@Wh^T)
__device__ __align__(256) __half g_trrp[NRELTAB * 2 * DD];
// g_tqr16: rel_emb[q_rel]@Wqr^T + bias, fp16
__device__ __align__(256) __half g_tqr16[BB * DD];

// ---------------------------------------------------------------------------
// Fused front kernel.
//  blocks [0, NGEMM_BLOCKS): zero d_out slice + dual-output SGEMM tile
//     -> g_h16 (interleaved fp16). Near fp32-FFMA roofline.
//  blocks [NGEMM_BLOCKS, +NPROJ_BLOCKS): relation projections, 4 rows/block.
// ---------------------------------------------------------------------------
__global__ __launch_bounds__(GEMM_THREADS)
void fused_pre_kernel(const float* __restrict__ hidden,
                      const float* __restrict__ Ws,
                      const float* __restrict__ Wh,
                      const float* __restrict__ emb,
                      const float* __restrict__ Wr,
                      const float* __restrict__ Wqr,
                      const float* __restrict__ bias,
                      const int* __restrict__ qrel,
                      float* __restrict__ out) {
    extern __shared__ float sm[];
    int t = threadIdx.x;

    if (blockIdx.x < NGEMM_BLOCKS) {
        // zero the output buffer (edge kernel REDs into it)
        {
            int i = blockIdx.x * GEMM_THREADS + t;
            int stride = NGEMM_BLOCKS * GEMM_THREADS;
            float4* p = (float4*)out;
            const int n4 = NN * DD / 4;
            for (int j = i; j < n4; j += stride)
                p[j] = make_float4(0.f, 0.f, 0.f, 0.f);
        }

        float* Asm = sm;                 // [128][64]
        float* Wt1 = sm + BM * DD;       // Ws^T as [k][a]
        float* Wt2 = Wt1 + DD * DD;      // Wh^T as [k][a]

        for (int i = t; i < DD * DD / 4; i += GEMM_THREADS) {
            int a = i >> 4, k = (i & 15) * 4;
            float4 w = ((const float4*)Ws)[i];
            Wt1[(k + 0) * DD + a] = w.x; Wt1[(k + 1) * DD + a] = w.y;
            Wt1[(k + 2) * DD + a] = w.z; Wt1[(k + 3) * DD + a] = w.w;
            float4 v = ((const float4*)Wh)[i];
            Wt2[(k + 0) * DD + a] = v.x; Wt2[(k + 1) * DD + a] = v.y;
            Wt2[(k + 2) * DD + a] = v.z; Wt2[(k + 3) * DD + a] = v.w;
        }
        int row0 = blockIdx.x * BM;
        for (int i = t; i < BM * DD / 4; i += GEMM_THREADS) {
            int m = i >> 4;
            float4 v = make_float4(0.f, 0.f, 0.f, 0.f);
            if (row0 + m < NN)
                v = ((const float4*)(hidden + (size_t)(row0 + m) * DD))[i & 15];
            ((float4*)Asm)[i] = v;
        }
        __syncthreads();

        int rt = t >> 4, ct = t & 15;
        const float* arow = Asm + rt * TM * DD;
        const float4* w1p = (const float4*)Wt1 + ct;
        const float4* w2p = (const float4*)Wt2 + ct;

        float4 acc1[TM], acc2[TM];
#pragma unroll
        for (int r = 0; r < TM; r++) {
            acc1[r] = make_float4(0.f, 0.f, 0.f, 0.f);
            acc2[r] = make_float4(0.f, 0.f, 0.f, 0.f);
        }

#pragma unroll 4
        for (int k = 0; k < DD; k++) {
            float4 w1 = w1p[k * 16];
            float4 w2 = w2p[k * 16];
#pragma unroll
            for (int r = 0; r < TM; r++) {
                float a = arow[r * DD + k];
                acc1[r].x = fmaf(a, w1.x, acc1[r].x);
                acc1[r].y = fmaf(a, w1.y, acc1[r].y);
                acc1[r].z = fmaf(a, w1.z, acc1[r].z);
                acc1[r].w = fmaf(a, w1.w, acc1[r].w);
                acc2[r].x = fmaf(a, w2.x, acc2[r].x);
                acc2[r].y = fmaf(a, w2.y, acc2[r].y);
                acc2[r].z = fmaf(a, w2.z, acc2[r].z);
                acc2[r].w = fmaf(a, w2.w, acc2[r].w);
            }
        }

#pragma unroll
        for (int r = 0; r < TM; r++) {
            int m = row0 + rt * TM + r;
            if (m < NN) {
                uint4 h;  // hsp 4 halves | hp2 4 halves (interleaved layout)
                ((__half2*)&h)[0] = __floats2half2_rn(acc1[r].x, acc1[r].y);
                ((__half2*)&h)[1] = __floats2half2_rn(acc1[r].z, acc1[r].w);
                ((__half2*)&h)[2] = __floats2half2_rn(acc2[r].x, acc2[r].y);
                ((__half2*)&h)[3] = __floats2half2_rn(acc2[r].z, acc2[r].w);
                ((uint4*)(g_h16 + (size_t)m * 2 * DD))[ct] = h;
            }
        }
        return;
    }

    // ---- relation projection path: 4 rows/block, 64 threads per row ----
    float* WrS  = sm;               // [64][65]
    float* WhS  = sm + DD * 65;     // [64][65]
    float* WqrS = sm + 2 * DD * 65; // [64][65]
    float* rows = sm + 3 * DD * 65; // [4][64]
    for (int i = t; i < DD * DD; i += GEMM_THREADS) {
        int r = i >> 6, c = i & 63;
        WrS [r * 65 + c] = Wr[i];
        WhS [r * 65 + c] = Wh[i];
        WqrS[r * 65 + c] = Wqr[i];
    }
    int sub = t >> 6, a = t & 63;
    int rid = (blockIdx.x - NGEMM_BLOCKS) * 4 + sub;
    bool valid = rid < NPROJ_ROWS;
    int seg = valid ? ((rid >= 2 * NRELTAB) ? 2 : (rid >= NRELTAB) ? 1 : 0) : 0;
    int r = rid - (seg == 2 ? 2 * NRELTAB : seg == 1 ? NRELTAB : 0);
    int src = valid ? (seg == 2 ? qrel[r] : r) : 0;
    rows[sub * DD + a] = emb[src * DD + a];
    __syncthreads();
    if (!valid) return;

    const float* W = (seg == 2) ? WqrS : (seg == 1) ? WhS : WrS;
    const float* rw = rows + sub * DD;
    float acc = (seg == 2) ? bias[a] : 0.f;
#pragma unroll
    for (int k = 0; k < DD; k++) acc = fmaf(rw[k], W[a * 65 + k], acc);

    __half h = __float2half(acc);
    if (seg == 2) {
        g_tqr16[r * DD + a] = h;
    } else {
        // interleaved: tr at halves 8*(a/4)+(a%4), rp2 at +4
        int pos = r * 2 * DD + 8 * (a >> 2) + (a & 3) + (seg == 1 ? 4 : 0);
        g_trrp[pos] = h;
    }
}

// ---------------------------------------------------------------------------
// Edge kernel: non-persistent (R5 geometry: NE/16 blocks x 256, occ ~84%)
// with the R6 fused fp16 layout (fewer L1tex wavefronts).
// Per warp (2 edges): idx 1 + h16 4 + trrp 4 + tq 2 + wv 2 + wb 1 + RED 4
// ~= 18 wavefronts (R5 was ~25).
//   alpha = sigmoid( dot(relu(hsp[sub] + tr[rel] + tqr[r_idx]), w) + b )
//   red.global.add.v4.f32 of alpha*(hp2[sub] + rp2[rel]) directly into OUT
// ---------------------------------------------------------------------------
__global__ __launch_bounds__(256)
void edge_kernel(const int* __restrict__ edges,
                 const float* __restrict__ walpha_w,
                 const float* __restrict__ walpha_b,
                 float* __restrict__ out) {
    unsigned gtid = blockIdx.x * blockDim.x + threadIdx.x;
    unsigned eid = gtid >> 4;  // exact: grid covers NE
    int l = gtid & 15;

    // lane-split index load + broadcast (cols 0,2,4,5 of the 6-int row)
    const int* e = edges + (size_t)eid * 6;
    int v = 0;
    if (l < 4) v = __ldg(e + ((0x5420u >> (l * 4)) & 0xF));  // 0,2,4,5
    int r_idx = __shfl_sync(0xffffffffu, v, 0, 16);
    int rel   = __shfl_sync(0xffffffffu, v, 1, 16);
    int sub   = __shfl_sync(0xffffffffu, v, 2, 16);
    int obj   = __shfl_sync(0xffffffffu, v, 3, 16);

    uint4 h  = __ldg((const uint4*)(g_h16 + (size_t)sub * 2 * DD) + l);
    uint4 tt = __ldg((const uint4*)(g_trrp + rel * 2 * DD) + l);
    uint2 tq = __ldg((const uint2*)(g_tqr16 + r_idx * DD) + l);
    float4 wv = __ldg((const float4*)walpha_w + l);

    float2 a0 = __half22float2(*(const __half2*)&h.x);   // hsp[4l..4l+1]
    float2 a1 = __half22float2(*(const __half2*)&h.y);   // hsp[4l+2..3]
    float2 b0 = __half22float2(*(const __half2*)&h.z);   // hp2[4l..4l+1]
    float2 b1 = __half22float2(*(const __half2*)&h.w);
    float2 t0 = __half22float2(*(const __half2*)&tt.x);  // tr
    float2 t1 = __half22float2(*(const __half2*)&tt.y);
    float2 r0 = __half22float2(*(const __half2*)&tt.z);  // rp2
    float2 r1 = __half22float2(*(const __half2*)&tt.w);
    float2 q0 = __half22float2(*(const __half2*)&tq.x);
    float2 q1 = __half22float2(*(const __half2*)&tq.y);

    float p0 = fmaxf(a0.x + t0.x + q0.x, 0.f);
    float p1 = fmaxf(a0.y + t0.y + q0.y, 0.f);
    float p2 = fmaxf(a1.x + t1.x + q1.x, 0.f);
    float p3 = fmaxf(a1.y + t1.y + q1.y, 0.f);
    float part = fmaf(p0, wv.x, fmaf(p1, wv.y, fmaf(p2, wv.z, p3 * wv.w)));
#pragma unroll
    for (int o = 8; o > 0; o >>= 1)
        part += __shfl_xor_sync(0xffffffffu, part, o);

    float alpha = 1.f / (1.f + __expf(-(part + __ldg(walpha_b))));

    float m0 = alpha * (b0.x + r0.x);
    float m1 = alpha * (b0.y + r0.y);
    float m2 = alpha * (b1.x + r1.x);
    float m3 = alpha * (b1.y + r1.y);

    float* dst = out + (size_t)obj * DD + l * 4;
    asm volatile("red.global.add.v4.f32 [%0], {%1, %2, %3, %4};"
                 :: "l"(dst), "f"(m0), "f"(m1), "f"(m2), "f"(m3)
                 : "memory");
}

// ---------------------------------------------------------------------------
// Inputs (metadata order):
//  0 q_sub[8] i32, 1 q_rel[8] i32, 2 hidden[100000,64] f32, 3 edges[1000000,6] i32,
//  4 nodes[100000,2] i32, 5 old_nodes_new_idx[50000] i32, 6 batchsize i32,
//  7 rel_emb[401,64] f32, 8 Ws[64,64], 9 Wr[64,64], 10 Wqr_w[64,64], 11 Wqr_b[64],
// 12 walpha_w[1,64], 13 walpha_b[1], 14 Wh[64,64]
// Output: hidden_new[100000,64] f32
// ---------------------------------------------------------------------------
extern "C" void kernel_launch(void* const* d_in, const int* in_sizes, int n_in,
                              void* d_out, int out_size) {
    const int*   q_rel    = (const int*)d_in[1];
    const float* hidden   = (const float*)d_in[2];
    const int*   edges    = (const int*)d_in[3];
    const float* rel_emb  = (const float*)d_in[7];
    const float* Ws       = (const float*)d_in[8];
    const float* Wr       = (const float*)d_in[9];
    const float* Wqr_w    = (const float*)d_in[10];
    const float* Wqr_b    = (const float*)d_in[11];
    const float* walpha_w = (const float*)d_in[12];
    const float* walpha_b = (const float*)d_in[13];
    const float* Wh       = (const float*)d_in[14];
    float* out = (float*)d_out;

    cudaFuncSetAttribute(fused_pre_kernel,
                         cudaFuncAttributeMaxDynamicSharedMemorySize, PRE_SMEM);

    fused_pre_kernel<<<NGEMM_BLOCKS + NPROJ_BLOCKS, GEMM_THREADS, PRE_SMEM>>>(
        hidden, Ws, Wh, rel_emb, Wr, Wqr_w, Wqr_b, q_rel, out);
    edge_kernel<<<NE / 16, 256>>>(edges, walpha_w, walpha_b, out);
}

// round 8
// speedup vs baseline: 1.1403x; 1.0419x over previous
#include <cuda_runtime.h>
#include <cuda_fp16.h>
#include <mma.h>

using namespace nvcuda;

#define NN 100000
#define PADN 100096          // NN rounded up to 128 (wmma tile safety)
#define NE 1000000
#define DD 64
#define NRELTAB 401
#define BB 8

#define BM 128
#define GEMM_THREADS 256
#define NGEMM_BLOCKS (PADN / BM)                 // 782
#define NPROJ_ROWS (2 * NRELTAB + BB)            // 810
#define NPROJ_BLOCKS ((NPROJ_ROWS + 3) / 4)      // 203
#define PRE_SMEM 65536                           // 8 warps * 16*128 fp32

// Scratch (static device globals — no runtime allocation).
__device__ __align__(256) __half g_hidden16[PADN * DD];   // fp16(hidden), zero-padded rows
__device__ __align__(256) __half g_W16[DD * 2 * DD];      // W16[k][a]: a<64 Ws^T, a>=64 Wh^T
// g_h16: per node, 128 halves: for l in 0..15: hsp[4l..4l+3] then hp2[4l..4l+3]
__device__ __align__(256) __half g_h16[PADN * 2 * DD];
// g_trrp: per relation, 128 halves: for l: tr[4l..4l+3], rp2[4l..4l+3]
__device__ __align__(256) __half g_trrp[NRELTAB * 2 * DD];
__device__ __align__(256) __half g_tqr16[BB * DD];        // rel_emb[q_rel]@Wqr^T + bias

// ---------------------------------------------------------------------------
// Conversion kernel: zero d_out, hidden -> fp16 (padded), build W16.
// Pure memory streaming (~64MB) ~ 8us.
// ---------------------------------------------------------------------------
__global__ void conv_kernel(const float* __restrict__ hidden,
                            const float* __restrict__ Ws,
                            const float* __restrict__ Wh,
                            float* __restrict__ out) {
    int tid = blockIdx.x * blockDim.x + threadIdx.x;
    int stride = gridDim.x * blockDim.x;

    // zero output buffer (edge kernel REDs into it)
    {
        float4* p = (float4*)out;
        const int n4 = NN * DD / 4;
        for (int j = tid; j < n4; j += stride)
            p[j] = make_float4(0.f, 0.f, 0.f, 0.f);
    }
    // hidden -> fp16 (zero-pad rows NN..PADN)
    {
        __half2* dst = (__half2*)g_hidden16;
        const int n2 = PADN * DD / 2;
        for (int j = tid; j < n2; j += stride) {
            int row = j >> 5;            // DD/2 = 32 half2 per row
            float2 v = make_float2(0.f, 0.f);
            if (row < NN) v = ((const float2*)(hidden + (size_t)row * DD))[j & 31];
            dst[j] = __floats2half2_rn(v.x, v.y);
        }
    }
    // W16[k][a] = a<64 ? Ws[a][k] : Wh[a-64][k]
    for (int i = tid; i < DD * 2 * DD; i += stride) {
        int k = i >> 7, a = i & 127;
        float w = (a < DD) ? Ws[a * DD + k] : Wh[(a - DD) * DD + k];
        g_W16[k * 2 * DD + a] = __float2half(w);
    }
}

// ---------------------------------------------------------------------------
// Fused GEMM (tensor-core) + relation projections.
//  blocks [0, NGEMM_BLOCKS): hidden16[128 rows] @ W16[64][128] -> g_h16.
//    8 warps; warp w does rows [w*16, w*16+16) x 128 cols via wmma 16x16x16
//    (f16 in, f32 accum). Epilogue stages C in per-warp smem (8KB each),
//    converts to fp16 interleaved layout, one uint4 store per lane-row.
//  blocks [NGEMM_BLOCKS, +NPROJ_BLOCKS): fp32 relation projections (4 rows/blk)
//    -> g_trrp / g_tqr16 (unchanged from R7).
// ---------------------------------------------------------------------------
__global__ __launch_bounds__(GEMM_THREADS)
void fused_pre_kernel(const float* __restrict__ emb,
                      const float* __restrict__ Wr,
                      const float* __restrict__ WhF,
                      const float* __restrict__ Wqr,
                      const float* __restrict__ bias,
                      const int* __restrict__ qrel) {
    extern __shared__ float sm[];
    int t = threadIdx.x;

    if (blockIdx.x < NGEMM_BLOCKS) {
        int w = t >> 5;              // warp 0..7
        int lane = t & 31;
        int row0 = blockIdx.x * BM + w * 16;

        wmma::fragment<wmma::accumulator, 16, 16, 16, float> c[8];
#pragma unroll
        for (int j = 0; j < 8; j++) wmma::fill_fragment(c[j], 0.f);

        const __half* Abase = g_hidden16 + (size_t)row0 * DD;
#pragma unroll
        for (int kk = 0; kk < 4; kk++) {
            wmma::fragment<wmma::matrix_a, 16, 16, 16, __half, wmma::row_major> a;
            wmma::load_matrix_sync(a, Abase + kk * 16, DD);
#pragma unroll
            for (int j = 0; j < 8; j++) {
                wmma::fragment<wmma::matrix_b, 16, 16, 16, __half, wmma::row_major> b;
                wmma::load_matrix_sync(b, g_W16 + kk * 16 * 128 + j * 16, 128);
                wmma::mma_sync(c[j], a, b, c[j]);
            }
        }

        // epilogue: per-warp smem [16][128] fp32 -> interleaved fp16 g_h16
        float* csm = sm + w * 16 * 128;
#pragma unroll
        for (int j = 0; j < 8; j++)
            wmma::store_matrix_sync(csm + j * 16, c[j], 128, wmma::mem_row_major);
        __syncwarp();

        int l16 = lane & 15, rh = lane >> 4;
#pragma unroll
        for (int it = 0; it < 8; it++) {
            int r = it * 2 + rh;
            const float* rp = csm + r * 128;
            float4 hs = *(const float4*)(rp + 4 * l16);        // hsp cols 4l..4l+3
            float4 hp = *(const float4*)(rp + 64 + 4 * l16);   // hp2 cols
            uint4 hbits;
            ((__half2*)&hbits)[0] = __floats2half2_rn(hs.x, hs.y);
            ((__half2*)&hbits)[1] = __floats2half2_rn(hs.z, hs.w);
            ((__half2*)&hbits)[2] = __floats2half2_rn(hp.x, hp.y);
            ((__half2*)&hbits)[3] = __floats2half2_rn(hp.z, hp.w);
            *(uint4*)(g_h16 + (size_t)(row0 + r) * 128 + l16 * 8) = hbits;
        }
        return;
    }

    // ---- relation projection path: 4 rows/block, 64 threads per row ----
    float* WrS  = sm;               // [64][65]
    float* WhS  = sm + DD * 65;     // [64][65]
    float* WqrS = sm + 2 * DD * 65; // [64][65]
    float* rows = sm + 3 * DD * 65; // [4][64]
    for (int i = t; i < DD * DD; i += GEMM_THREADS) {
        int r = i >> 6, c = i & 63;
        WrS [r * 65 + c] = Wr[i];
        WhS [r * 65 + c] = WhF[i];
        WqrS[r * 65 + c] = Wqr[i];
    }
    int sub = t >> 6, a = t & 63;
    int rid = (blockIdx.x - NGEMM_BLOCKS) * 4 + sub;
    bool valid = rid < NPROJ_ROWS;
    int seg = valid ? ((rid >= 2 * NRELTAB) ? 2 : (rid >= NRELTAB) ? 1 : 0) : 0;
    int r = rid - (seg == 2 ? 2 * NRELTAB : seg == 1 ? NRELTAB : 0);
    int src = valid ? (seg == 2 ? qrel[r] : r) : 0;
    rows[sub * DD + a] = emb[src * DD + a];
    __syncthreads();
    if (!valid) return;

    const float* W = (seg == 2) ? WqrS : (seg == 1) ? WhS : WrS;
    const float* rw = rows + sub * DD;
    float acc = (seg == 2) ? bias[a] : 0.f;
#pragma unroll
    for (int k = 0; k < DD; k++) acc = fmaf(rw[k], W[a * 65 + k], acc);

    __half h = __float2half(acc);
    if (seg == 2) {
        g_tqr16[r * DD + a] = h;
    } else {
        int pos = r * 2 * DD + 8 * (a >> 2) + (a & 3) + (seg == 1 ? 4 : 0);
        g_trrp[pos] = h;
    }
}

// ---------------------------------------------------------------------------
// Edge kernel (unchanged from R7: 80.7us, occ 81%, L1tex-bound).
// ---------------------------------------------------------------------------
__global__ __launch_bounds__(256)
void edge_kernel(const int* __restrict__ edges,
                 const float* __restrict__ walpha_w,
                 const float* __restrict__ walpha_b,
                 float* __restrict__ out) {
    unsigned gtid = blockIdx.x * blockDim.x + threadIdx.x;
    unsigned eid = gtid >> 4;
    int l = gtid & 15;

    const int* e = edges + (size_t)eid * 6;
    int v = 0;
    if (l < 4) v = __ldg(e + ((0x5420u >> (l * 4)) & 0xF));  // cols 0,2,4,5
    int r_idx = __shfl_sync(0xffffffffu, v, 0, 16);
    int rel   = __shfl_sync(0xffffffffu, v, 1, 16);
    int sub   = __shfl_sync(0xffffffffu, v, 2, 16);
    int obj   = __shfl_sync(0xffffffffu, v, 3, 16);

    uint4 h  = __ldg((const uint4*)(g_h16 + (size_t)sub * 2 * DD) + l);
    uint4 tt = __ldg((const uint4*)(g_trrp + rel * 2 * DD) + l);
    uint2 tq = __ldg((const uint2*)(g_tqr16 + r_idx * DD) + l);
    float4 wv = __ldg((const float4*)walpha_w + l);

    float2 a0 = __half22float2(*(const __half2*)&h.x);
    float2 a1 = __half22float2(*(const __half2*)&h.y);
    float2 b0 = __half22float2(*(const __half2*)&h.z);
    float2 b1 = __half22float2(*(const __half2*)&h.w);
    float2 t0 = __half22float2(*(const __half2*)&tt.x);
    float2 t1 = __half22float2(*(const __half2*)&tt.y);
    float2 r0 = __half22float2(*(const __half2*)&tt.z);
    float2 r1 = __half22float2(*(const __half2*)&tt.w);
    float2 q0 = __half22float2(*(const __half2*)&tq.x);
    float2 q1 = __half22float2(*(const __half2*)&tq.y);

    float p0 = fmaxf(a0.x + t0.x + q0.x, 0.f);
    float p1 = fmaxf(a0.y + t0.y + q0.y, 0.f);
    float p2 = fmaxf(a1.x + t1.x + q1.x, 0.f);
    float p3 = fmaxf(a1.y + t1.y + q1.y, 0.f);
    float part = fmaf(p0, wv.x, fmaf(p1, wv.y, fmaf(p2, wv.z, p3 * wv.w)));
#pragma unroll
    for (int o = 8; o > 0; o >>= 1)
        part += __shfl_xor_sync(0xffffffffu, part, o);

    float alpha = 1.f / (1.f + __expf(-(part + __ldg(walpha_b))));

    float m0 = alpha * (b0.x + r0.x);
    float m1 = alpha * (b0.y + r0.y);
    float m2 = alpha * (b1.x + r1.x);
    float m3 = alpha * (b1.y + r1.y);

    float* dst = out + (size_t)obj * DD + l * 4;
    asm volatile("red.global.add.v4.f32 [%0], {%1, %2, %3, %4};"
                 :: "l"(dst), "f"(m0), "f"(m1), "f"(m2), "f"(m3)
                 : "memory");
}

// ---------------------------------------------------------------------------
// Inputs (metadata order):
//  0 q_sub[8] i32, 1 q_rel[8] i32, 2 hidden[100000,64] f32, 3 edges[1000000,6] i32,
//  4 nodes[100000,2] i32, 5 old_nodes_new_idx[50000] i32, 6 batchsize i32,
//  7 rel_emb[401,64] f32, 8 Ws[64,64], 9 Wr[64,64], 10 Wqr_w[64,64], 11 Wqr_b[64],
// 12 walpha_w[1,64], 13 walpha_b[1], 14 Wh[64,64]
// Output: hidden_new[100000,64] f32
// ---------------------------------------------------------------------------
extern "C" void kernel_launch(void* const* d_in, const int* in_sizes, int n_in,
                              void* d_out, int out_size) {
    const int*   q_rel    = (const int*)d_in[1];
    const float* hidden   = (const float*)d_in[2];
    const int*   edges    = (const int*)d_in[3];
    const float* rel_emb  = (const float*)d_in[7];
    const float* Ws       = (const float*)d_in[8];
    const float* Wr       = (const float*)d_in[9];
    const float* Wqr_w    = (const float*)d_in[10];
    const float* Wqr_b    = (const float*)d_in[11];
    const float* walpha_w = (const float*)d_in[12];
    const float* walpha_b = (const float*)d_in[13];
    const float* Wh       = (const float*)d_in[14];
    float* out = (float*)d_out;

    cudaFuncSetAttribute(fused_pre_kernel,
                         cudaFuncAttributeMaxDynamicSharedMemorySize, PRE_SMEM);

    conv_kernel<<<2048, 256>>>(hidden, Ws, Wh, out);
    fused_pre_kernel<<<NGEMM_BLOCKS + NPROJ_BLOCKS, GEMM_THREADS, PRE_SMEM>>>(
        rel_emb, Wr, Wh, Wqr_w, Wqr_b, q_rel);
    edge_kernel<<<NE / 16, 256>>>(edges, walpha_w, walpha_b, out);
}